// round 2
// baseline (speedup 1.0000x reference)
#include <cuda_runtime.h>
#include <cstdint>

// 2D Haar DWT, fp32, input (8, 64, 512, 512) -> 4x (8, 64, 256, 256)
// Output d_out = [ll | lh | hl | hh], each 8*64*256*256 floats.
//
// HBM-bound (R1: 6.82 TB/s, 86% DRAM). R2: widen to 2x8 input patch per
// thread -> 4x LDG.128 + 4x STG.128, all with streaming (evict-first)
// cache hints since there is zero reuse.

#define PLANES      512          // 8 * 64
#define IN_W        512
#define IN_H        512
#define OUT_W       256
#define OUT_H       256
#define PLANE_IN_F4   (IN_W * IN_H / 4)    // 65536 float4 per input plane
#define ROW_IN_F4     (IN_W / 4)           // 128 float4 per input row
#define PLANE_OUT_F4  (OUT_W * OUT_H / 4)  // 16384 float4 per output plane
#define ROW_OUT_F4    (OUT_W / 4)          // 64 float4 per output row
#define SUBBAND_ELEMS (PLANES * OUT_W * OUT_H)  // 33554432 floats per subband

__global__ __launch_bounds__(256)
void dwt2d_haar_kernel(const float4* __restrict__ x4,
                       float4* __restrict__ ll,
                       float4* __restrict__ lh,
                       float4* __restrict__ hl,
                       float4* __restrict__ hh)
{
    // One thread = one (plane, out_row, out_col_quad): reads 2x8 input patch
    // (4 x float4), writes 1 float4 to each of the 4 subbands.
    unsigned tid = blockIdx.x * blockDim.x + threadIdx.x;
    // total = 512 planes * 256 rows * 64 col-quads = 8,388,608 (exact grid)

    unsigned ox4 = tid & (ROW_OUT_F4 - 1);          // 0..63
    unsigned t1  = tid >> 6;
    unsigned oy  = t1 & (OUT_H - 1);                // 0..255
    unsigned p   = t1 >> 8;                         // 0..511

    unsigned in_base = p * PLANE_IN_F4 + (2u * oy) * ROW_IN_F4 + 2u * ox4;

    // Front-batched independent loads (MLP=4), streaming hint (no reuse).
    float4 r0a = __ldcs(&x4[in_base]);                    // row 2y,   cols 8x..8x+3
    float4 r0b = __ldcs(&x4[in_base + 1]);                // row 2y,   cols 8x+4..8x+7
    float4 r1a = __ldcs(&x4[in_base + ROW_IN_F4]);        // row 2y+1, cols 8x..8x+3
    float4 r1b = __ldcs(&x4[in_base + ROW_IN_F4 + 1]);    // row 2y+1, cols 8x+4..8x+7

    const float half = 0.5f;

    // pixel k uses a=top-even, b=top-odd, c=bot-even, d=bot-odd
    float a0 = r0a.x, b0 = r0a.y, c0 = r1a.x, d0 = r1a.y;
    float a1 = r0a.z, b1 = r0a.w, c1 = r1a.z, d1 = r1a.w;
    float a2 = r0b.x, b2 = r0b.y, c2 = r1b.x, d2 = r1b.y;
    float a3 = r0b.z, b3 = r0b.w, c3 = r1b.z, d3 = r1b.w;

    float4 vll, vlh, vhl, vhh;
    vll.x = (a0 + b0 + c0 + d0) * half;
    vll.y = (a1 + b1 + c1 + d1) * half;
    vll.z = (a2 + b2 + c2 + d2) * half;
    vll.w = (a3 + b3 + c3 + d3) * half;

    vlh.x = (c0 + d0 - a0 - b0) * half;
    vlh.y = (c1 + d1 - a1 - b1) * half;
    vlh.z = (c2 + d2 - a2 - b2) * half;
    vlh.w = (c3 + d3 - a3 - b3) * half;

    vhl.x = (b0 + d0 - a0 - c0) * half;
    vhl.y = (b1 + d1 - a1 - c1) * half;
    vhl.z = (b2 + d2 - a2 - c2) * half;
    vhl.w = (b3 + d3 - a3 - c3) * half;

    vhh.x = (a0 + d0 - b0 - c0) * half;
    vhh.y = (a1 + d1 - b1 - c1) * half;
    vhh.z = (a2 + d2 - b2 - c2) * half;
    vhh.w = (a3 + d3 - b3 - c3) * half;

    unsigned o = p * PLANE_OUT_F4 + oy * ROW_OUT_F4 + ox4;
    __stcs(&ll[o], vll);
    __stcs(&lh[o], vlh);
    __stcs(&hl[o], vhl);
    __stcs(&hh[o], vhh);
}

extern "C" void kernel_launch(void* const* d_in, const int* in_sizes, int n_in,
                              void* d_out, int out_size)
{
    const float4* x4 = (const float4*)d_in[0];
    float* out = (float*)d_out;

    float4* ll = (float4*)(out + 0ull * SUBBAND_ELEMS);
    float4* lh = (float4*)(out + 1ull * SUBBAND_ELEMS);
    float4* hl = (float4*)(out + 2ull * SUBBAND_ELEMS);
    float4* hh = (float4*)(out + 3ull * SUBBAND_ELEMS);

    const unsigned total_threads = PLANES * OUT_H * ROW_OUT_F4;  // 8,388,608
    const unsigned block = 256;
    const unsigned grid = total_threads / block;                 // 32,768

    dwt2d_haar_kernel<<<grid, block>>>(x4, ll, lh, hl, hh);
}